// round 4
// baseline (speedup 1.0000x reference)
#include <cuda_runtime.h>
#include <cstdint>

// Problem constants
#define DMK   1024          // input dim (K of the GEMM)
#define BB    8             // batch (M of the GEMM)
#define VN    32767         // internal nodes = V-1 (N of the GEMM)
#define DEPTH 15
#define TT    1024

// Phase-1 tiling
#define WARPS          4
#define ROWS_PER_WARP  64   // 2 rows per lane
#define ROWS_PER_BLOCK (WARPS * ROWS_PER_WARP)          // 256
#define KC             64   // k-chunk per stage
#define LDW            68   // smem row stride in floats (pad for conflict-free LDS.128)
#define STAGES         2
#define TILE_FLOATS    (ROWS_PER_WARP * LDW)            // 4352
#define SMEM_FLOATS    (WARPS * STAGES * TILE_FLOATS + DMK * BB)
#define NBLOCKS        ((VN + ROWS_PER_BLOCK - 1) / ROWS_PER_BLOCK)  // 128

// Scratch: sigmoid table S[node][b], node-major so phase-1 stores are 2x STG.128/row.
__device__ float S_buf[32768 * 8];

// ---------- f32x2 helpers (sm_103a packed fp32 FMA; ptxas never emits from C++) ----
__device__ __forceinline__ unsigned long long pack2(float v) {
    unsigned long long r;
    asm("mov.b64 %0, {%1, %1};" : "=l"(r) : "f"(v));
    return r;
}
__device__ __forceinline__ void ffma2(unsigned long long& d, unsigned long long a,
                                      unsigned long long b) {
    asm("fma.rn.f32x2 %0, %1, %2, %0;" : "+l"(d) : "l"(a), "l"(b));
}
__device__ __forceinline__ void unpack2(unsigned long long v, float& lo, float& hi) {
    asm("mov.b64 {%0, %1}, %2;" : "=f"(lo), "=f"(hi) : "l"(v));
}
__device__ __forceinline__ void cp16(float* sdst, const float* gsrc) {
    uint32_t s = (uint32_t)__cvta_generic_to_shared(sdst);
    asm volatile("cp.async.cg.shared.global [%0], [%1], 16;" :: "r"(s), "l"(gsrc));
}

// ======================= Phase 1: S = sigmoid(W @ x^T + bias) ======================
// Block = 128 threads (4 warps). Each warp owns 64 rows exclusively, sweeps all of
// K=1024 in 16 double-buffered cp.async chunks. lane -> rows {lane, lane+32}; per-lane
// accumulators cover all 8 batch items as 4 f32x2 pairs -> no cross-lane reduction.
__global__ void __launch_bounds__(128, 1)
hs_logits(const float* __restrict__ x, const float* __restrict__ W,
          const float* __restrict__ bias) {
    extern __shared__ float sm[];
    const int tid  = threadIdx.x;
    const int lane = tid & 31;
    const int warp = tid >> 5;

    float* xT = sm + WARPS * STAGES * TILE_FLOATS;  // xT[k][b], f32x2-pair friendly

    // Transpose x (8x1024 -> k-major, 32 KB) once per block; coalesced gmem reads.
    for (int i = tid; i < DMK * BB; i += 128) {
        int b = i >> 10;            // x is [B, DM] row-major
        int k = i & (DMK - 1);
        xT[k * 8 + b] = x[i];
    }
    __syncthreads();

    float*    wtile = sm + warp * STAGES * TILE_FLOATS;
    const int rb    = blockIdx.x * ROWS_PER_BLOCK + warp * ROWS_PER_WARP;

    // Stage one 64-row x 64-k chunk (16 KB/warp) via cp.async; rows clamped at VN-1.
    auto stage = [&](int c, int s) {
        float* dst = wtile + s * TILE_FLOATS;
        #pragma unroll
        for (int j = 0; j < 32; ++j) {
            int id = lane + 32 * j;          // 1024 float4s per chunk
            int r  = id >> 4;                // row within tile (0..63)
            int q  = id & 15;                // k-quad (0..15)
            int gr = rb + r;
            if (gr > VN - 1) gr = VN - 1;    // clamp: valid addr, store suppressed later
            cp16(dst + r * LDW + q * 4, W + (size_t)gr * DMK + c * KC + q * 4);
        }
        asm volatile("cp.async.commit_group;");
    };

    unsigned long long acc0[4] = {0ull, 0ull, 0ull, 0ull};
    unsigned long long acc1[4] = {0ull, 0ull, 0ull, 0ull};

    stage(0, 0);
    const int NCH = DMK / KC;  // 16
    for (int c = 0; c < NCH; ++c) {
        __syncwarp();  // all lanes done reading the buffer we are about to overwrite
        if (c + 1 < NCH) {
            stage(c + 1, (c + 1) & 1);
            asm volatile("cp.async.wait_group 1;");
        } else {
            asm volatile("cp.async.wait_group 0;");
        }
        __syncwarp();  // chunk c visible to all lanes

        const float* ws = wtile + (c & 1) * TILE_FLOATS;
        const float* xk = xT + c * KC * 8;

        #pragma unroll
        for (int kk = 0; kk < KC; kk += 4) {
            float4 w0 = *(const float4*)(ws + lane * LDW + kk);         // row lane
            float4 w1 = *(const float4*)(ws + (lane + 32) * LDW + kk);  // row lane+32
            float w0a[4] = {w0.x, w0.y, w0.z, w0.w};
            float w1a[4] = {w1.x, w1.y, w1.z, w1.w};
            #pragma unroll
            for (int j = 0; j < 4; ++j) {
                const double2 xab = *(const double2*)(xk + (kk + j) * 8);      // b0..b3
                const double2 xcd = *(const double2*)(xk + (kk + j) * 8 + 4);  // b4..b7
                unsigned long long x01 = __double_as_longlong(xab.x);
                unsigned long long x23 = __double_as_longlong(xab.y);
                unsigned long long x45 = __double_as_longlong(xcd.x);
                unsigned long long x67 = __double_as_longlong(xcd.y);
                unsigned long long p0 = pack2(w0a[j]);
                ffma2(acc0[0], p0, x01); ffma2(acc0[1], p0, x23);
                ffma2(acc0[2], p0, x45); ffma2(acc0[3], p0, x67);
                unsigned long long p1 = pack2(w1a[j]);
                ffma2(acc1[0], p1, x01); ffma2(acc1[1], p1, x23);
                ffma2(acc1[2], p1, x45); ffma2(acc1[3], p1, x67);
            }
        }
    }

    // Epilogue: + bias, sigmoid, store S[node][0..7] as two float4s.
    const int grs[2] = {rb + lane, rb + lane + 32};
    #pragma unroll
    for (int rr = 0; rr < 2; ++rr) {
        int gr = grs[rr];
        if (gr >= VN) continue;
        const unsigned long long* acc = (rr == 0) ? acc0 : acc1;
        float bb = bias[gr];
        float s[8];
        #pragma unroll
        for (int p = 0; p < 4; ++p) unpack2(acc[p], s[2 * p], s[2 * p + 1]);
        #pragma unroll
        for (int i = 0; i < 8; ++i) {
            float z = s[i] + bb;
            s[i] = 1.0f / (1.0f + __expf(-z));
        }
        float4* dst = (float4*)(S_buf + (size_t)gr * 8);
        dst[0] = make_float4(s[0], s[1], s[2], s[3]);
        dst[1] = make_float4(s[4], s[5], s[6], s[7]);
    }
}

// ======================= Phase 2: gather + product over path ======================
__global__ void hs_gather(const int* __restrict__ ids, const int* __restrict__ paths,
                          float* __restrict__ out) {
    int idx = blockIdx.x * blockDim.x + threadIdx.x;
    if (idx >= BB * TT) return;
    int b  = idx >> 10;  // ids/out are [B, T] row-major
    int id = ids[idx];
    const int* p = paths + (size_t)id * DEPTH;
    float pr = 1.0f;
    #pragma unroll
    for (int d = 0; d < DEPTH; ++d) pr *= S_buf[(size_t)p[d] * 8 + b];
    out[idx] = pr;
}

// =================================== launch =======================================
extern "C" void kernel_launch(void* const* d_in, const int* in_sizes, int n_in,
                              void* d_out, int out_size) {
    // Resolve inputs by element count (robust to ordering); x precedes ids among the
    // two 8192-element inputs (setup_inputs dict order).
    const float* x = nullptr; const int* ids = nullptr; const int* paths = nullptr;
    const float* W = nullptr; const float* bias = nullptr;
    for (int i = 0; i < n_in; ++i) {
        long long s = in_sizes[i];
        if (s == (long long)VN * DMK)       W     = (const float*)d_in[i];
        else if (s == (long long)32768 * DEPTH) paths = (const int*)d_in[i];
        else if (s == VN)                   bias  = (const float*)d_in[i];
        else if (s == (long long)BB * TT) {
            if (!x) x = (const float*)d_in[i];
            else    ids = (const int*)d_in[i];
        }
    }

    cudaFuncSetAttribute(hs_logits, cudaFuncAttributeMaxDynamicSharedMemorySize,
                         SMEM_FLOATS * 4);
    hs_logits<<<NBLOCKS, 128, SMEM_FLOATS * 4>>>(x, W, bias);
    hs_gather<<<(BB * TT + 127) / 128, 128>>>(ids, paths, (float*)d_out);
}